// round 11
// baseline (speedup 1.0000x reference)
#include <cuda_runtime.h>
#include <cuda_fp16.h>
#include <mma.h>
using namespace nvcuda;

#define NUSER 100000
#define NITEM 50000
#define NN    150000
#define EE    2400000
#define F     64
#define Q     4096
#define GR    128               // rows per gemm block
#define NEG_SLOPE 0.2f

// ---------------- device scratch (no allocs allowed) ----------------
__device__ __align__(16) float  g_x[2][NN * F];     // [0]=online, [1]=target (fp32)
__device__ __align__(16) __half g_h16[2][NN * F];   // dense fp16 h per encoder (row = 128B)
__device__ __align__(8)  float2 g_as2[NN];          // (as_online, as_target) fp32
__device__ __align__(8)  float2 g_ad2[NN];          // (ad_online, ad_target) fp32
__device__ int g_rowptr[NN + 1];
__device__ int g_fill[NN];   // .bss zero at load; re-zeroed by agg2 each launch
__device__ int g_col[EE];

__device__ __forceinline__ float lrelu(float v) { return fmaxf(v, NEG_SLOPE * v); }

// ---------------- CSR build ----------------
__global__ void hist_kernel(const int* __restrict__ ei) {
    int i = blockIdx.x * blockDim.x + threadIdx.x;
    if (i < EE) atomicAdd(&g_fill[__ldcs(ei + EE + i)], 1);
}

__global__ void scan_kernel() {
    __shared__ int sb[1024];
    int t = threadIdx.x;
    const int CH = 147;
    int start = t * CH;
    int end = min(start + CH, NN);
    int s = 0;
    for (int i = start; i < end; i++) s += g_fill[i];
    sb[t] = s;
    __syncthreads();
    for (int o = 1; o < 1024; o <<= 1) {
        int v = 0;
        if (t >= o) v = sb[t - o];
        __syncthreads();
        if (t >= o) sb[t] += v;
        __syncthreads();
    }
    int run = (t == 0) ? 0 : sb[t - 1];
    for (int i = start; i < end; i++) {
        int cnt = g_fill[i];
        g_rowptr[i] = run;
        g_fill[i]   = run;
        run += cnt;
    }
    if (t == 1023) g_rowptr[NN] = sb[1023];
}

__global__ void scatter_kernel(const int* __restrict__ ei) {
    int i = blockIdx.x * blockDim.x + threadIdx.x;
    if (i < EE) {
        int d = __ldcs(ei + EE + i);
        int pos = atomicAdd(&g_fill[d], 1);
        g_col[pos] = __ldcs(ei + i);
    }
}

// ---------------- WMMA gemm (h = x @ W, fp16 in / fp32 acc) + fused dots ----
// Reads X from (Xu | Xi) split at row NUSER (layer 1: raw embeddings;
// layers 2+: g_x[enc] halves) with streaming loads.
// smem layout (40KB): [0,8K) W half; [8K,24K) X half; [8K,40K) C float (unions X).
__global__ void __launch_bounds__(256) gemm_dots_kernel(
    const float* __restrict__ Xu0, const float* __restrict__ Xi0,
    const float* __restrict__ Xu1, const float* __restrict__ Xi1,
    const float* __restrict__ Wo, const float* __restrict__ Wt,
    const float* __restrict__ aso, const float* __restrict__ ado,
    const float* __restrict__ ast, const float* __restrict__ adt) {
    int enc = blockIdx.y;
    const float* W   = enc ? Wt  : Wo;
    const float* avs = enc ? ast : aso;
    const float* avd = enc ? adt : ado;
    const float* Xu  = enc ? Xu1 : Xu0;
    const float* Xi  = enc ? Xi1 : Xi0;

    __shared__ __align__(16) char smem[40960];
    half*  Wh = (half*)smem;
    half*  Xh = (half*)(smem + 8192);
    float* Cs = (float*)(smem + 8192);

    int tid = threadIdx.x;
    int r0  = blockIdx.x * GR;

    // load W (64x64 fp32 -> fp16)
    {
        const float4* W4 = (const float4*)W;
#pragma unroll
        for (int i = 0; i < 4; i++) {
            int idx = tid + i * 256;              // float4 index, 1024 total
            float4 v = W4[idx];
            half2* dst = (half2*)(Wh + idx * 4);
            dst[0] = __floats2half2_rn(v.x, v.y);
            dst[1] = __floats2half2_rn(v.z, v.w);
        }
    }
    // load X tile (GR x 64 fp32 -> fp16), user/item split, streaming
    {
#pragma unroll
        for (int i = 0; i < 8; i++) {
            int idx = tid + i * 256;              // float4 index, 2048 total
            int row = idx >> 4;
            int q   = idx & 15;
            int gr  = r0 + row;
            float4 v = make_float4(0.f, 0.f, 0.f, 0.f);
            if (gr < NUSER)      v = __ldcs((const float4*)(Xu + (size_t)gr * F) + q);
            else if (gr < NN)    v = __ldcs((const float4*)(Xi + (size_t)(gr - NUSER) * F) + q);
            half2* dst = (half2*)(Xh + idx * 4);
            dst[0] = __floats2half2_rn(v.x, v.y);
            dst[1] = __floats2half2_rn(v.z, v.w);
        }
    }
    __syncthreads();

    int wid = tid >> 5, lane = tid & 31;

    wmma::fragment<wmma::accumulator, 16, 16, 16, float> cfrag[4];
#pragma unroll
    for (int n = 0; n < 4; n++) wmma::fill_fragment(cfrag[n], 0.0f);
#pragma unroll
    for (int k = 0; k < 4; k++) {
        wmma::fragment<wmma::matrix_a, 16, 16, 16, half, wmma::row_major> afrag;
        wmma::load_matrix_sync(afrag, Xh + (wid * 16) * 64 + k * 16, 64);
#pragma unroll
        for (int n = 0; n < 4; n++) {
            wmma::fragment<wmma::matrix_b, 16, 16, 16, half, wmma::row_major> bfrag;
            wmma::load_matrix_sync(bfrag, Wh + (k * 16) * 64 + n * 16, 64);
            wmma::mma_sync(cfrag[n], afrag, bfrag, cfrag[n]);
        }
    }
    __syncthreads();   // everyone done reading Xh before Cs overwrites it
#pragma unroll
    for (int n = 0; n < 4; n++)
        wmma::store_matrix_sync(Cs + (wid * 16) * 64 + n * 16, cfrag[n], 64, wmma::mem_row_major);
    __syncthreads();

    // dense fp16 h store: thread (c) writes column c of 32 rows — warp covers
    // 64B contiguous per row, full sectors, no cross-CTA sharing.
    int c = tid & 63;
    int rbase = (tid >> 6) * 32;
    __half* Hd = g_h16[enc];
#pragma unroll
    for (int i = 0; i < 32; i++) {
        int r = rbase + i;
        int gr = r0 + r;
        if (gr < NN) Hd[(size_t)gr * F + c] = __float2half(Cs[r * 64 + c]);
    }

    // fused dots (fp32): 8 warps x 16 rows
    float a0 = avs[lane], a1 = avs[32 + lane];
    float d0 = avd[lane], d1 = avd[32 + lane];
#pragma unroll
    for (int rr = 0; rr < 16; rr++) {
        int r = wid * 16 + rr;
        float h0 = Cs[r * 64 + lane];
        float h1 = Cs[r * 64 + 32 + lane];
        float s  = h0 * a0 + h1 * a1;
        float dd = h0 * d0 + h1 * d1;
#pragma unroll
        for (int o = 16; o; o >>= 1) {
            s  += __shfl_xor_sync(0xffffffffu, s,  o);
            dd += __shfl_xor_sync(0xffffffffu, dd, o);
        }
        int gr = r0 + r;
        if (lane == 0 && gr < NN) {
            ((float*)g_as2)[2 * gr + enc] = s;
            ((float*)g_ad2)[2 * gr + enc] = dd;
        }
    }
}

// ---------------- single-pass dual-encoder GAT aggregation (fp16 messages) ----
__global__ void __launch_bounds__(256) agg2_kernel(const float* __restrict__ bo,
                                                   const float* __restrict__ bt) {
    int d = (blockIdx.x * blockDim.x + threadIdx.x) >> 5;
    int lane = threadIdx.x & 31;
    if (d >= NN) return;

    const unsigned* h0p = (const unsigned*)g_h16[0];   // lane l: half2 (2l, 2l+1)
    const unsigned* h1p = (const unsigned*)g_h16[1];

    int s0 = g_rowptr[d];
    int s1 = g_rowptr[d + 1];
    float2 adv = g_ad2[d];
    float2 asv = g_as2[d];
    float m0 = lrelu(asv.x + adv.x);     // running maxes; self weight starts at 1
    float m1 = lrelu(asv.y + adv.y);

    unsigned hs0 = h0p[(size_t)d * 32 + lane];
    unsigned hs1 = h1p[(size_t)d * 32 + lane];
    float2 f0 = __half22float2(*(__half2*)&hs0);
    float2 f1 = __half22float2(*(__half2*)&hs1);
    float acc0x = f0.x, acc0y = f0.y;    // self message, weight exp(e_self - m) = 1
    float acc1x = f1.x, acc1y = f1.y;
    float den0 = (lane == 0) ? 1.f : 0.f;
    float den1 = den0;

    for (int base = s0; base < s1; base += 32) {
        int k = base + lane;
        bool valid = k < s1;
        int s = valid ? __ldcs(&g_col[k]) : 0;
        float e0 = -1e30f, e1 = -1e30f;
        if (valid) {
            float2 a = g_as2[s];
            e0 = lrelu(a.x + adv.x);
            e1 = lrelu(a.y + adv.y);
        }
        // warp-wide chunk maxes
        float c0 = e0, c1 = e1;
#pragma unroll
        for (int o = 16; o; o >>= 1) {
            c0 = fmaxf(c0, __shfl_xor_sync(0xffffffffu, c0, o));
            c1 = fmaxf(c1, __shfl_xor_sync(0xffffffffu, c1, o));
        }
        if (c0 > m0) { float sc = __expf(m0 - c0); acc0x *= sc; acc0y *= sc; den0 *= sc; m0 = c0; }
        if (c1 > m1) { float sc = __expf(m1 - c1); acc1x *= sc; acc1y *= sc; den1 *= sc; m1 = c1; }

        float w0 = valid ? __expf(e0 - m0) : 0.f;
        float w1 = valid ? __expf(e1 - m1) : 0.f;
        den0 += w0;
        den1 += w1;

        int cnt = min(32, s1 - base);
        int padded = (cnt + 3) & ~3;     // padded lanes carry w=0, s=0 -> no-ops
        for (int j = 0; j < padded; j += 4) {
            int sj0 = __shfl_sync(0xffffffffu, s, j + 0);
            int sj1 = __shfl_sync(0xffffffffu, s, j + 1);
            int sj2 = __shfl_sync(0xffffffffu, s, j + 2);
            int sj3 = __shfl_sync(0xffffffffu, s, j + 3);
            unsigned u00 = h0p[(size_t)sj0 * 32 + lane];
            unsigned u01 = h1p[(size_t)sj0 * 32 + lane];
            unsigned u10 = h0p[(size_t)sj1 * 32 + lane];
            unsigned u11 = h1p[(size_t)sj1 * 32 + lane];
            unsigned u20 = h0p[(size_t)sj2 * 32 + lane];
            unsigned u21 = h1p[(size_t)sj2 * 32 + lane];
            unsigned u30 = h0p[(size_t)sj3 * 32 + lane];
            unsigned u31 = h1p[(size_t)sj3 * 32 + lane];
            float a0w = __shfl_sync(0xffffffffu, w0, j + 0);
            float b0w = __shfl_sync(0xffffffffu, w1, j + 0);
            float a1w = __shfl_sync(0xffffffffu, w0, j + 1);
            float b1w = __shfl_sync(0xffffffffu, w1, j + 1);
            float a2w = __shfl_sync(0xffffffffu, w0, j + 2);
            float b2w = __shfl_sync(0xffffffffu, w1, j + 2);
            float a3w = __shfl_sync(0xffffffffu, w0, j + 3);
            float b3w = __shfl_sync(0xffffffffu, w1, j + 3);
            float2 p, q;
            p = __half22float2(*(__half2*)&u00); q = __half22float2(*(__half2*)&u01);
            acc0x = fmaf(a0w, p.x, acc0x);  acc0y = fmaf(a0w, p.y, acc0y);
            acc1x = fmaf(b0w, q.x, acc1x);  acc1y = fmaf(b0w, q.y, acc1y);
            p = __half22float2(*(__half2*)&u10); q = __half22float2(*(__half2*)&u11);
            acc0x = fmaf(a1w, p.x, acc0x);  acc0y = fmaf(a1w, p.y, acc0y);
            acc1x = fmaf(b1w, q.x, acc1x);  acc1y = fmaf(b1w, q.y, acc1y);
            p = __half22float2(*(__half2*)&u20); q = __half22float2(*(__half2*)&u21);
            acc0x = fmaf(a2w, p.x, acc0x);  acc0y = fmaf(a2w, p.y, acc0y);
            acc1x = fmaf(b2w, q.x, acc1x);  acc1y = fmaf(b2w, q.y, acc1y);
            p = __half22float2(*(__half2*)&u30); q = __half22float2(*(__half2*)&u31);
            acc0x = fmaf(a3w, p.x, acc0x);  acc0y = fmaf(a3w, p.y, acc0y);
            acc1x = fmaf(b3w, q.x, acc1x);  acc1y = fmaf(b3w, q.y, acc1y);
        }
    }
#pragma unroll
    for (int o = 16; o; o >>= 1) {
        den0 += __shfl_xor_sync(0xffffffffu, den0, o);
        den1 += __shfl_xor_sync(0xffffffffu, den1, o);
    }
    float inv0 = 1.f / den0;
    float inv1 = 1.f / den1;

    float2 o0, o1;
    o0.x = acc0x * inv0 + bo[2 * lane];
    o0.y = acc0y * inv0 + bo[2 * lane + 1];
    o1.x = acc1x * inv1 + bt[2 * lane];
    o1.y = acc1y * inv1 + bt[2 * lane + 1];
    __stcs(&((float2*)g_x[0])[(size_t)d * 32 + lane], o0);
    __stcs(&((float2*)g_x[1])[(size_t)d * 32 + lane], o1);

    if (lane == 0) g_fill[d] = 0;   // reset counts for the next launch (idempotent)
}

// ---------------- predictor + output assembly ----------------
__global__ void __launch_bounds__(256) final_kernel(const float* __restrict__ pW,
                                                    const float* __restrict__ pb,
                                                    const int* __restrict__ user,
                                                    const int* __restrict__ item,
                                                    float* __restrict__ out) {
    __shared__ float Ws[64 * 65];
    __shared__ float rows[4 * 64];
    int tid = threadIdx.x;
    bool isU = blockIdx.x < (Q / 4);
    int qb = (isU ? blockIdx.x : blockIdx.x - (Q / 4)) * 4;

    for (int i = tid; i < 4096; i += 256) Ws[(i >> 6) * 65 + (i & 63)] = pW[i];

    int qr = tid >> 6, c = tid & 63;
    int q = qb + qr;
    int node = isU ? user[q] : (NUSER + item[q]);
    rows[qr * 64 + c] = g_x[0][(size_t)node * F + c];
    __syncthreads();

    float acc = pb[c];
#pragma unroll
    for (int k = 0; k < 64; k++) acc = fmaf(rows[qr * 64 + k], Ws[c * 65 + k], acc);

    size_t base = isU ? 0 : (size_t)2 * Q * F;
    out[base + (size_t)q * F + c] = acc;                                  // predicted
    out[base + (size_t)Q * F + (size_t)q * F + c] = g_x[1][(size_t)node * F + c];  // target
}

// ---------------- host ----------------
extern "C" void kernel_launch(void* const* d_in, const int* in_sizes, int n_in,
                              void* d_out, int out_size) {
    const float *uembo, *iembo, *Wo, *aso, *ado, *bo;
    const float *uembt, *iembt, *Wt, *ast, *adt, *bt;
    const float *pW, *pb;
    const int *user, *item, *ei;

    if (in_sizes[0] == Q) {  // setup_inputs dict order
        user  = (const int*)d_in[0];
        item  = (const int*)d_in[1];
        ei    = (const int*)d_in[2];
        uembo = (const float*)d_in[3];  iembo = (const float*)d_in[4];
        Wo    = (const float*)d_in[5];
        aso   = (const float*)d_in[6];  ado   = (const float*)d_in[7];  bo = (const float*)d_in[8];
        uembt = (const float*)d_in[9];  iembt = (const float*)d_in[10];
        Wt    = (const float*)d_in[11];
        ast   = (const float*)d_in[12]; adt   = (const float*)d_in[13]; bt = (const float*)d_in[14];
        pW    = (const float*)d_in[15]; pb    = (const float*)d_in[16];
    } else {                 // reference signature order
        uembo = (const float*)d_in[0];  iembo = (const float*)d_in[1];
        Wo    = (const float*)d_in[2];
        aso   = (const float*)d_in[3];  ado   = (const float*)d_in[4];  bo = (const float*)d_in[5];
        uembt = (const float*)d_in[6];  iembt = (const float*)d_in[7];
        Wt    = (const float*)d_in[8];
        ast   = (const float*)d_in[9];  adt   = (const float*)d_in[10]; bt = (const float*)d_in[11];
        pW    = (const float*)d_in[12]; pb    = (const float*)d_in[13];
        user  = (const int*)d_in[14];
        item  = (const int*)d_in[15];
        ei    = (const int*)d_in[16];
    }
    float* out = (float*)d_out;

    // CSR build (g_fill is zero: .bss at load, re-zeroed by agg2 each launch)
    hist_kernel<<<EE / 256, 256>>>(ei);
    scan_kernel<<<1, 1024>>>();
    scatter_kernel<<<EE / 256, 256>>>(ei);

    const int GEMM_BLOCKS = (NN + GR - 1) / GR;  // 1172
    const int WARP_BLOCKS = NN / 8;              // 18750

    static float* gx_base = nullptr;
    if (!gx_base) cudaGetSymbolAddress((void**)&gx_base, g_x);

    for (int l = 0; l < 3; l++) {
        dim3 gg(GEMM_BLOCKS, 2);
        const float *Xu0, *Xi0, *Xu1, *Xi1;
        if (l == 0) {
            Xu0 = uembo; Xi0 = iembo; Xu1 = uembt; Xi1 = iembt;
        } else {
            Xu0 = gx_base;
            Xi0 = gx_base + (size_t)NUSER * F;
            Xu1 = gx_base + (size_t)NN * F;
            Xi1 = gx_base + (size_t)NN * F + (size_t)NUSER * F;
        }
        gemm_dots_kernel<<<gg, 256>>>(Xu0, Xi0, Xu1, Xi1,
                                      Wo + (size_t)l * F * F, Wt + (size_t)l * F * F,
                                      aso + l * F, ado + l * F, ast + l * F, adt + l * F);
        agg2_kernel<<<WARP_BLOCKS, 256>>>(bo + l * F, bt + l * F);
    }

    final_kernel<<<2 * (Q / 4), 256>>>(pW, pb, user, item, out);
}

// round 13
// speedup vs baseline: 1.0123x; 1.0123x over previous
#include <cuda_runtime.h>
#include <cuda_fp16.h>
#include <mma.h>
using namespace nvcuda;

#define NUSER 100000
#define NITEM 50000
#define NN    150000
#define EE    2400000
#define F     64
#define Q     4096
#define GR    128               // rows per gemm block
#define NEG_SLOPE 0.2f

// ---------------- device scratch (no allocs allowed) ----------------
__device__ __align__(16) float  g_x[2][NN * F];     // [0]=online, [1]=target (fp32)
__device__ __align__(16) __half g_h16[2][NN * F];   // dense fp16 h per encoder (row = 128B)
__device__ __align__(8)  float2 g_as2[NN];          // (as_online, as_target) fp32
__device__ __align__(8)  float2 g_ad2[NN];          // (ad_online, ad_target) fp32
__device__ int g_rowptr[NN + 1];
__device__ int g_fill[NN];   // .bss zero at load; re-zeroed by agg2 each launch
__device__ int g_col[EE];

__device__ __forceinline__ float lrelu(float v) { return fmaxf(v, NEG_SLOPE * v); }

// ---------------- CSR build ----------------
__global__ void hist_kernel(const int* __restrict__ ei) {
    int i = blockIdx.x * blockDim.x + threadIdx.x;
    if (i < EE) atomicAdd(&g_fill[__ldcs(ei + EE + i)], 1);
}

__global__ void scan_kernel() {
    __shared__ int sb[1024];
    int t = threadIdx.x;
    const int CH = 147;
    int start = t * CH;
    int end = min(start + CH, NN);
    int s = 0;
    for (int i = start; i < end; i++) s += g_fill[i];
    sb[t] = s;
    __syncthreads();
    for (int o = 1; o < 1024; o <<= 1) {
        int v = 0;
        if (t >= o) v = sb[t - o];
        __syncthreads();
        if (t >= o) sb[t] += v;
        __syncthreads();
    }
    int run = (t == 0) ? 0 : sb[t - 1];
    for (int i = start; i < end; i++) {
        int cnt = g_fill[i];
        g_rowptr[i] = run;
        g_fill[i]   = run;
        run += cnt;
    }
    if (t == 1023) g_rowptr[NN] = sb[1023];
}

__global__ void scatter_kernel(const int* __restrict__ ei) {
    int i = blockIdx.x * blockDim.x + threadIdx.x;
    if (i < EE) {
        int d = __ldcs(ei + EE + i);
        int pos = atomicAdd(&g_fill[d], 1);
        g_col[pos] = __ldcs(ei + i);
    }
}

// ---------------- WMMA gemm (h = x @ W, fp16 in / fp32 acc) + fused dots ----
// smem layout (40KB): [0,8K) W half; [8K,24K) X half; [8K,40K) C float (unions X).
__global__ void __launch_bounds__(256) gemm_dots_kernel(
    const float* __restrict__ Xu0, const float* __restrict__ Xi0,
    const float* __restrict__ Xu1, const float* __restrict__ Xi1,
    const float* __restrict__ Wo, const float* __restrict__ Wt,
    const float* __restrict__ aso, const float* __restrict__ ado,
    const float* __restrict__ ast, const float* __restrict__ adt) {
    int enc = blockIdx.y;
    const float* W   = enc ? Wt  : Wo;
    const float* avs = enc ? ast : aso;
    const float* avd = enc ? adt : ado;
    const float* Xu  = enc ? Xu1 : Xu0;
    const float* Xi  = enc ? Xi1 : Xi0;

    __shared__ __align__(16) char smem[40960];
    half*  Wh = (half*)smem;
    half*  Xh = (half*)(smem + 8192);
    float* Cs = (float*)(smem + 8192);

    int tid = threadIdx.x;
    int r0  = blockIdx.x * GR;

    // load W (64x64 fp32 -> fp16), packed STS.64
    {
        const float4* W4 = (const float4*)W;
#pragma unroll
        for (int i = 0; i < 4; i++) {
            int idx = tid + i * 256;              // float4 index, 1024 total
            float4 v = W4[idx];
            __half2 a = __floats2half2_rn(v.x, v.y);
            __half2 b = __floats2half2_rn(v.z, v.w);
            *(uint2*)(Wh + idx * 4) = make_uint2(*(unsigned*)&a, *(unsigned*)&b);
        }
    }
    // load X tile (GR x 64 fp32 -> fp16), user/item split, streaming, packed STS.64
    {
#pragma unroll
        for (int i = 0; i < 8; i++) {
            int idx = tid + i * 256;              // float4 index, 2048 total
            int row = idx >> 4;
            int q   = idx & 15;
            int gr  = r0 + row;
            float4 v = make_float4(0.f, 0.f, 0.f, 0.f);
            if (gr < NUSER)      v = __ldcs((const float4*)(Xu + (size_t)gr * F) + q);
            else if (gr < NN)    v = __ldcs((const float4*)(Xi + (size_t)(gr - NUSER) * F) + q);
            __half2 a = __floats2half2_rn(v.x, v.y);
            __half2 b = __floats2half2_rn(v.z, v.w);
            *(uint2*)(Xh + idx * 4) = make_uint2(*(unsigned*)&a, *(unsigned*)&b);
        }
    }
    __syncthreads();

    int wid = tid >> 5, lane = tid & 31;

    wmma::fragment<wmma::accumulator, 16, 16, 16, float> cfrag[4];
#pragma unroll
    for (int n = 0; n < 4; n++) wmma::fill_fragment(cfrag[n], 0.0f);
#pragma unroll
    for (int k = 0; k < 4; k++) {
        wmma::fragment<wmma::matrix_a, 16, 16, 16, half, wmma::row_major> afrag;
        wmma::load_matrix_sync(afrag, Xh + (wid * 16) * 64 + k * 16, 64);
#pragma unroll
        for (int n = 0; n < 4; n++) {
            wmma::fragment<wmma::matrix_b, 16, 16, 16, half, wmma::row_major> bfrag;
            wmma::load_matrix_sync(bfrag, Wh + (k * 16) * 64 + n * 16, 64);
            wmma::mma_sync(cfrag[n], afrag, bfrag, cfrag[n]);
        }
    }
    __syncthreads();   // everyone done reading Xh before Cs overwrites it
#pragma unroll
    for (int n = 0; n < 4; n++)
        wmma::store_matrix_sync(Cs + (wid * 16) * 64 + n * 16, cfrag[n], 64, wmma::mem_row_major);
    __syncthreads();

    // dense fp16 h store, vectorized: thread handles 4 (row, 8-col-group) items:
    // 2x LDS.128 + convert + 1x STG.128 each. XOR swizzle on group avoids the
    // full-row 2-way bank pattern lining up across phases.
    __half* Hd = g_h16[enc];
#pragma unroll
    for (int i = 0; i < 4; i++) {
        int idx = tid + i * 256;                 // 0..1023 items
        int r   = idx >> 3;
        int g   = ((idx & 7) + r) & 7;           // swizzled column group (bijective per row)
        int gr  = r0 + r;
        if (gr < NN) {
            const float4* src = (const float4*)(Cs + r * 64 + g * 8);
            float4 f0 = src[0], f1 = src[1];
            __half2 a  = __floats2half2_rn(f0.x, f0.y);
            __half2 b  = __floats2half2_rn(f0.z, f0.w);
            __half2 c2 = __floats2half2_rn(f1.x, f1.y);
            __half2 d2 = __floats2half2_rn(f1.z, f1.w);
            *(uint4*)(Hd + (size_t)gr * F + g * 8) =
                make_uint4(*(unsigned*)&a, *(unsigned*)&b, *(unsigned*)&c2, *(unsigned*)&d2);
        }
    }

    // fused dots (fp32): 8 warps x 16 rows
    float a0 = avs[lane], a1 = avs[32 + lane];
    float d0 = avd[lane], d1 = avd[32 + lane];
#pragma unroll
    for (int rr = 0; rr < 16; rr++) {
        int r = wid * 16 + rr;
        float h0 = Cs[r * 64 + lane];
        float h1 = Cs[r * 64 + 32 + lane];
        float s  = h0 * a0 + h1 * a1;
        float dd = h0 * d0 + h1 * d1;
#pragma unroll
        for (int o = 16; o; o >>= 1) {
            s  += __shfl_xor_sync(0xffffffffu, s,  o);
            dd += __shfl_xor_sync(0xffffffffu, dd, o);
        }
        int gr = r0 + r;
        if (lane == 0 && gr < NN) {
            ((float*)g_as2)[2 * gr + enc] = s;
            ((float*)g_ad2)[2 * gr + enc] = dd;
        }
    }
}

// ---------------- single-pass dual-encoder GAT aggregation ------------------
// Split-lane scheme: lanes 0-15 accumulate encoder 0 (4 cols each, one LDG.64
// per edge), lanes 16-31 encoder 1. Softmax logits computed warp-wide as before.
// Row stride: 64 halves = 16 uint2 -> index = node*16 + li.
__global__ void __launch_bounds__(256) agg2_kernel(const float* __restrict__ bo,
                                                   const float* __restrict__ bt) {
    int d = (blockIdx.x * blockDim.x + threadIdx.x) >> 5;
    int lane = threadIdx.x & 31;
    if (d >= NN) return;

    int encSel = lane >> 4;          // 0: lanes 0-15, 1: lanes 16-31
    int li     = lane & 15;          // cols 4*li .. 4*li+3 of encoder encSel
    const uint2* hsel = encSel ? (const uint2*)g_h16[1] : (const uint2*)g_h16[0];

    int s0 = g_rowptr[d];
    int s1 = g_rowptr[d + 1];
    float2 adv = g_ad2[d];
    float2 asv = g_as2[d];
    float m0 = lrelu(asv.x + adv.x);     // running maxes; self weight starts at 1
    float m1 = lrelu(asv.y + adv.y);

    uint2 hd = hsel[(size_t)d * 16 + li];
    float2 pa = __half22float2(*(__half2*)&hd.x);
    float2 pb = __half22float2(*(__half2*)&hd.y);
    float acc0 = pa.x, acc1 = pa.y, acc2 = pb.x, acc3 = pb.y;  // self message (w=1)
    float den0 = (lane == 0) ? 1.f : 0.f;
    float den1 = den0;

    for (int base = s0; base < s1; base += 32) {
        int k = base + lane;
        bool valid = k < s1;
        int s = valid ? __ldcs(&g_col[k]) : 0;
        float e0 = -1e30f, e1 = -1e30f;
        if (valid) {
            float2 a = g_as2[s];
            e0 = lrelu(a.x + adv.x);
            e1 = lrelu(a.y + adv.y);
        }
        // warp-wide chunk maxes
        float c0 = e0, c1 = e1;
#pragma unroll
        for (int o = 16; o; o >>= 1) {
            c0 = fmaxf(c0, __shfl_xor_sync(0xffffffffu, c0, o));
            c1 = fmaxf(c1, __shfl_xor_sync(0xffffffffu, c1, o));
        }
        if (c0 > m0) {
            float sc = __expf(m0 - c0);
            den0 *= sc;
            if (encSel == 0) { acc0 *= sc; acc1 *= sc; acc2 *= sc; acc3 *= sc; }
            m0 = c0;
        }
        if (c1 > m1) {
            float sc = __expf(m1 - c1);
            den1 *= sc;
            if (encSel == 1) { acc0 *= sc; acc1 *= sc; acc2 *= sc; acc3 *= sc; }
            m1 = c1;
        }

        float w0 = valid ? __expf(e0 - m0) : 0.f;
        float w1 = valid ? __expf(e1 - m1) : 0.f;
        den0 += w0;
        den1 += w1;

        int cnt = min(32, s1 - base);
        int padded = (cnt + 3) & ~3;     // padded lanes carry w=0, s=0 -> no-ops
        for (int j = 0; j < padded; j += 4) {
            int sj0 = __shfl_sync(0xffffffffu, s, j + 0);
            int sj1 = __shfl_sync(0xffffffffu, s, j + 1);
            int sj2 = __shfl_sync(0xffffffffu, s, j + 2);
            int sj3 = __shfl_sync(0xffffffffu, s, j + 3);
            uint2 v0 = hsel[(size_t)sj0 * 16 + li];
            uint2 v1 = hsel[(size_t)sj1 * 16 + li];
            uint2 v2 = hsel[(size_t)sj2 * 16 + li];
            uint2 v3 = hsel[(size_t)sj3 * 16 + li];
            float w00 = __shfl_sync(0xffffffffu, w0, j + 0);
            float w10 = __shfl_sync(0xffffffffu, w1, j + 0);
            float w01 = __shfl_sync(0xffffffffu, w0, j + 1);
            float w11 = __shfl_sync(0xffffffffu, w1, j + 1);
            float w02 = __shfl_sync(0xffffffffu, w0, j + 2);
            float w12 = __shfl_sync(0xffffffffu, w1, j + 2);
            float w03 = __shfl_sync(0xffffffffu, w0, j + 3);
            float w13 = __shfl_sync(0xffffffffu, w1, j + 3);
            float ws0 = encSel ? w10 : w00;
            float ws1 = encSel ? w11 : w01;
            float ws2 = encSel ? w12 : w02;
            float ws3 = encSel ? w13 : w03;
            float2 p, q;
            p = __half22float2(*(__half2*)&v0.x); q = __half22float2(*(__half2*)&v0.y);
            acc0 = fmaf(ws0, p.x, acc0); acc1 = fmaf(ws0, p.y, acc1);
            acc2 = fmaf(ws0, q.x, acc2); acc3 = fmaf(ws0, q.y, acc3);
            p = __half22float2(*(__half2*)&v1.x); q = __half22float2(*(__half2*)&v1.y);
            acc0 = fmaf(ws1, p.x, acc0); acc1 = fmaf(ws1, p.y, acc1);
            acc2 = fmaf(ws1, q.x, acc2); acc3 = fmaf(ws1, q.y, acc3);
            p = __half22float2(*(__half2*)&v2.x); q = __half22float2(*(__half2*)&v2.y);
            acc0 = fmaf(ws2, p.x, acc0); acc1 = fmaf(ws2, p.y, acc1);
            acc2 = fmaf(ws2, q.x, acc2); acc3 = fmaf(ws2, q.y, acc3);
            p = __half22float2(*(__half2*)&v3.x); q = __half22float2(*(__half2*)&v3.y);
            acc0 = fmaf(ws3, p.x, acc0); acc1 = fmaf(ws3, p.y, acc1);
            acc2 = fmaf(ws3, q.x, acc2); acc3 = fmaf(ws3, q.y, acc3);
        }
    }
#pragma unroll
    for (int o = 16; o; o >>= 1) {
        den0 += __shfl_xor_sync(0xffffffffu, den0, o);
        den1 += __shfl_xor_sync(0xffffffffu, den1, o);
    }
    float inv = encSel ? (1.f / den1) : (1.f / den0);

    const float* bsel = encSel ? bt : bo;
    float4 b4 = ((const float4*)bsel)[li];
    float4 o;
    o.x = acc0 * inv + b4.x;
    o.y = acc1 * inv + b4.y;
    o.z = acc2 * inv + b4.z;
    o.w = acc3 * inv + b4.w;
    __stcs(&((float4*)g_x[encSel])[(size_t)d * 16 + li], o);

    if (lane == 0) g_fill[d] = 0;   // reset counts for the next launch (idempotent)
}

// ---------------- predictor + output assembly ----------------
__global__ void __launch_bounds__(256) final_kernel(const float* __restrict__ pW,
                                                    const float* __restrict__ pb,
                                                    const int* __restrict__ user,
                                                    const int* __restrict__ item,
                                                    float* __restrict__ out) {
    __shared__ float Ws[64 * 65];
    __shared__ float rows[4 * 64];
    int tid = threadIdx.x;
    bool isU = blockIdx.x < (Q / 4);
    int qb = (isU ? blockIdx.x : blockIdx.x - (Q / 4)) * 4;

    for (int i = tid; i < 4096; i += 256) Ws[(i >> 6) * 65 + (i & 63)] = pW[i];

    int qr = tid >> 6, c = tid & 63;
    int q = qb + qr;
    int node = isU ? user[q] : (NUSER + item[q]);
    rows[qr * 64 + c] = g_x[0][(size_t)node * F + c];
    __syncthreads();

    float acc = pb[c];
#pragma unroll
    for (int k = 0; k < 64; k++) acc = fmaf(rows[qr * 64 + k], Ws[c * 65 + k], acc);

    size_t base = isU ? 0 : (size_t)2 * Q * F;
    out[base + (size_t)q * F + c] = acc;                                  // predicted
    out[base + (size_t)Q * F + (size_t)q * F + c] = g_x[1][(size_t)node * F + c];  // target
}

// ---------------- host ----------------
extern "C" void kernel_launch(void* const* d_in, const int* in_sizes, int n_in,
                              void* d_out, int out_size) {
    const float *uembo, *iembo, *Wo, *aso, *ado, *bo;
    const float *uembt, *iembt, *Wt, *ast, *adt, *bt;
    const float *pW, *pb;
    const int *user, *item, *ei;

    if (in_sizes[0] == Q) {  // setup_inputs dict order
        user  = (const int*)d_in[0];
        item  = (const int*)d_in[1];
        ei    = (const int*)d_in[2];
        uembo = (const float*)d_in[3];  iembo = (const float*)d_in[4];
        Wo    = (const float*)d_in[5];
        aso   = (const float*)d_in[6];  ado   = (const float*)d_in[7];  bo = (const float*)d_in[8];
        uembt = (const float*)d_in[9];  iembt = (const float*)d_in[10];
        Wt    = (const float*)d_in[11];
        ast   = (const float*)d_in[12]; adt   = (const float*)d_in[13]; bt = (const float*)d_in[14];
        pW    = (const float*)d_in[15]; pb    = (const float*)d_in[16];
    } else {                 // reference signature order
        uembo = (const float*)d_in[0];  iembo = (const float*)d_in[1];
        Wo    = (const float*)d_in[2];
        aso   = (const float*)d_in[3];  ado   = (const float*)d_in[4];  bo = (const float*)d_in[5];
        uembt = (const float*)d_in[6];  iembt = (const float*)d_in[7];
        Wt    = (const float*)d_in[8];
        ast   = (const float*)d_in[9];  adt   = (const float*)d_in[10]; bt = (const float*)d_in[11];
        pW    = (const float*)d_in[12]; pb    = (const float*)d_in[13];
        user  = (const int*)d_in[14];
        item  = (const int*)d_in[15];
        ei    = (const int*)d_in[16];
    }
    float* out = (float*)d_out;

    // CSR build (g_fill is zero: .bss at load, re-zeroed by agg2 each launch)
    hist_kernel<<<EE / 256, 256>>>(ei);
    scan_kernel<<<1, 1024>>>();
    scatter_kernel<<<EE / 256, 256>>>(ei);

    const int GEMM_BLOCKS = (NN + GR - 1) / GR;  // 1172
    const int WARP_BLOCKS = NN / 8;              // 18750

    static float* gx_base = nullptr;
    if (!gx_base) cudaGetSymbolAddress((void**)&gx_base, g_x);

    for (int l = 0; l < 3; l++) {
        dim3 gg(GEMM_BLOCKS, 2);
        const float *Xu0, *Xi0, *Xu1, *Xi1;
        if (l == 0) {
            Xu0 = uembo; Xi0 = iembo; Xu1 = uembt; Xi1 = iembt;
        } else {
            Xu0 = gx_base;
            Xi0 = gx_base + (size_t)NUSER * F;
            Xu1 = gx_base + (size_t)NN * F;
            Xi1 = gx_base + (size_t)NN * F + (size_t)NUSER * F;
        }
        gemm_dots_kernel<<<gg, 256>>>(Xu0, Xi0, Xu1, Xi1,
                                      Wo + (size_t)l * F * F, Wt + (size_t)l * F * F,
                                      aso + l * F, ado + l * F, ast + l * F, adt + l * F);
        agg2_kernel<<<WARP_BLOCKS, 256>>>(bo + l * F, bt + l * F);
    }

    final_kernel<<<2 * (Q / 4), 256>>>(pW, pb, user, item, out);
}

// round 14
// speedup vs baseline: 1.0950x; 1.0817x over previous
#include <cuda_runtime.h>
#include <cuda_fp16.h>
#include <mma.h>
using namespace nvcuda;

#define NUSER 100000
#define NITEM 50000
#define NN    150000
#define EE    2400000
#define F     64
#define Q     4096
#define GR    128               // rows per gemm block
#define CSTR  68                // padded Cs row stride (floats)
#define NEG_SLOPE 0.2f

// ---------------- device scratch (no allocs allowed) ----------------
__device__ __align__(16) float  g_x[2][NN * F];     // fp32 x (final layer output)
__device__ __align__(16) __half g_x16[2][NN * F];   // fp16 x hand-off (layers 1-2)
__device__ __align__(16) __half g_h16[2][NN * F];   // dense fp16 h per encoder
__device__ __align__(8)  float2 g_as2[NN];          // (as_online, as_target) fp32
__device__ __align__(8)  float2 g_ad2[NN];          // (ad_online, ad_target) fp32
__device__ int g_rowptr[NN + 1];
__device__ int g_fill[NN];   // .bss zero at load; re-zeroed by agg2 each launch
__device__ int g_col[EE];

__device__ __forceinline__ float lrelu(float v) { return fmaxf(v, NEG_SLOPE * v); }

// ---------------- CSR build ----------------
__global__ void hist_kernel(const int* __restrict__ ei) {
    int i = blockIdx.x * blockDim.x + threadIdx.x;
    if (i < EE) atomicAdd(&g_fill[__ldcs(ei + EE + i)], 1);
}

__global__ void scan_kernel() {
    __shared__ int sb[1024];
    int t = threadIdx.x;
    const int CH = 147;
    int start = t * CH;
    int end = min(start + CH, NN);
    int s = 0;
    for (int i = start; i < end; i++) s += g_fill[i];
    sb[t] = s;
    __syncthreads();
    for (int o = 1; o < 1024; o <<= 1) {
        int v = 0;
        if (t >= o) v = sb[t - o];
        __syncthreads();
        if (t >= o) sb[t] += v;
        __syncthreads();
    }
    int run = (t == 0) ? 0 : sb[t - 1];
    for (int i = start; i < end; i++) {
        int cnt = g_fill[i];
        g_rowptr[i] = run;
        g_fill[i]   = run;
        run += cnt;
    }
    if (t == 1023) g_rowptr[NN] = sb[1023];
}

__global__ void scatter_kernel(const int* __restrict__ ei) {
    int i = blockIdx.x * blockDim.x + threadIdx.x;
    if (i < EE) {
        int d = __ldcs(ei + EE + i);
        int pos = atomicAdd(&g_fill[d], 1);
        g_col[pos] = __ldcs(ei + i);
    }
}

// ---------------- WMMA gemm (h = x @ W, fp16 in / fp32 acc) + fused dots ----
// smem: [0,8K) W half (reused as As/Ad floats after MMA);
//       [8K,24.5K) X half;  [8K,43008) C float stride 68 (unions X).
__global__ void __launch_bounds__(256) gemm_dots_kernel(
    const void* __restrict__ Xu0, const void* __restrict__ Xi0,
    const void* __restrict__ Xu1, const void* __restrict__ Xi1,
    const float* __restrict__ Wo, const float* __restrict__ Wt,
    const float* __restrict__ aso, const float* __restrict__ ado,
    const float* __restrict__ ast, const float* __restrict__ adt,
    int xIsF16) {
    int enc = blockIdx.y;
    const float* W   = enc ? Wt  : Wo;
    const float* avs = enc ? ast : aso;
    const float* avd = enc ? adt : ado;
    const void* Xu   = enc ? Xu1 : Xu0;
    const void* Xi   = enc ? Xi1 : Xi0;

    __shared__ __align__(16) char smem[43008];
    half*  Wh   = (half*)smem;
    float* Avec = (float*)smem;          // 128 floats, written AFTER mma reads Wh
    half*  Xh   = (half*)(smem + 8192);
    float* Cs   = (float*)(smem + 8192); // stride CSTR

    int tid = threadIdx.x;
    int r0  = blockIdx.x * GR;

    // load W (64x64 fp32 -> fp16), packed STS.64
    {
        const float4* W4 = (const float4*)W;
#pragma unroll
        for (int i = 0; i < 4; i++) {
            int idx = tid + i * 256;
            float4 v = W4[idx];
            __half2 a = __floats2half2_rn(v.x, v.y);
            __half2 b = __floats2half2_rn(v.z, v.w);
            *(uint2*)(Wh + idx * 4) = make_uint2(*(unsigned*)&a, *(unsigned*)&b);
        }
    }
    // load X tile (GR x 64) -> fp16 smem; source fp32 (layer 0) or fp16 (layers 1+)
    if (xIsF16) {
        const uint4* XuH = (const uint4*)Xu;     // 8 halves per uint4, 8 per row
        const uint4* XiH = (const uint4*)Xi;
#pragma unroll
        for (int i = 0; i < 4; i++) {
            int idx = tid + i * 256;             // uint4 index, 1024 total
            int row = idx >> 3;
            int q   = idx & 7;
            int gr  = r0 + row;
            uint4 v = make_uint4(0u, 0u, 0u, 0u);
            if (gr < NUSER)   v = __ldcs(XuH + (size_t)gr * 8 + q);
            else if (gr < NN) v = __ldcs(XiH + (size_t)(gr - NUSER) * 8 + q);
            *(uint4*)(Xh + idx * 8) = v;
        }
    } else {
        const float4* XuF = (const float4*)Xu;
        const float4* XiF = (const float4*)Xi;
#pragma unroll
        for (int i = 0; i < 8; i++) {
            int idx = tid + i * 256;             // float4 index, 2048 total
            int row = idx >> 4;
            int q   = idx & 15;
            int gr  = r0 + row;
            float4 v = make_float4(0.f, 0.f, 0.f, 0.f);
            if (gr < NUSER)   v = __ldcs(XuF + (size_t)gr * 16 + q);
            else if (gr < NN) v = __ldcs(XiF + (size_t)(gr - NUSER) * 16 + q);
            __half2 a = __floats2half2_rn(v.x, v.y);
            __half2 b = __floats2half2_rn(v.z, v.w);
            *(uint2*)(Xh + idx * 4) = make_uint2(*(unsigned*)&a, *(unsigned*)&b);
        }
    }
    __syncthreads();

    int wid = tid >> 5;

    wmma::fragment<wmma::accumulator, 16, 16, 16, float> cfrag[4];
#pragma unroll
    for (int n = 0; n < 4; n++) wmma::fill_fragment(cfrag[n], 0.0f);
#pragma unroll
    for (int k = 0; k < 4; k++) {
        wmma::fragment<wmma::matrix_a, 16, 16, 16, half, wmma::row_major> afrag;
        wmma::load_matrix_sync(afrag, Xh + (wid * 16) * 64 + k * 16, 64);
#pragma unroll
        for (int n = 0; n < 4; n++) {
            wmma::fragment<wmma::matrix_b, 16, 16, 16, half, wmma::row_major> bfrag;
            wmma::load_matrix_sync(bfrag, Wh + (k * 16) * 64 + n * 16, 64);
            wmma::mma_sync(cfrag[n], afrag, bfrag, cfrag[n]);
        }
    }
    __syncthreads();   // all reads of Wh/Xh done

    // stage attention vectors into (now dead) W region; store C tiles
    if (tid < 64)       Avec[tid] = avs[tid];
    else if (tid < 128) Avec[tid] = avd[tid - 64];
#pragma unroll
    for (int n = 0; n < 4; n++)
        wmma::store_matrix_sync(Cs + (wid * 16) * CSTR + n * 16, cfrag[n], CSTR, wmma::mem_row_major);
    __syncthreads();

    // dense fp16 h store: thread handles 4 (row, 8-col-group) items.
    __half* Hd = g_h16[enc];
#pragma unroll
    for (int i = 0; i < 4; i++) {
        int idx = tid + i * 256;                 // 0..1023 items
        int r   = idx >> 3;
        int g   = ((idx & 7) + r) & 7;           // swizzled column group
        int gr  = r0 + r;
        if (gr < NN) {
            const float4* src = (const float4*)(Cs + r * CSTR + g * 8);
            float4 f0 = src[0], f1 = src[1];
            __half2 a  = __floats2half2_rn(f0.x, f0.y);
            __half2 b  = __floats2half2_rn(f0.z, f0.w);
            __half2 c2 = __floats2half2_rn(f1.x, f1.y);
            __half2 d2 = __floats2half2_rn(f1.z, f1.w);
            *(uint4*)(Hd + (size_t)gr * F + g * 8) =
                make_uint4(*(unsigned*)&a, *(unsigned*)&b, *(unsigned*)&c2, *(unsigned*)&d2);
        }
    }

    // shuffle-free dots: threads 0-127 -> as[row], threads 128-255 -> ad[row].
    // Row reads conflict-free thanks to stride 68 (bank shift 4r); a-vector
    // reads are warp-uniform broadcasts.
    {
        int r = tid & 127;
        bool isAd = tid >= 128;
        const float4* row4 = (const float4*)(Cs + r * CSTR);
        const float4* av4  = (const float4*)(Avec + (isAd ? 64 : 0));
        float acc = 0.f;
#pragma unroll
        for (int i = 0; i < 16; i++) {
            float4 c4 = row4[i];
            float4 a4 = av4[i];
            acc += c4.x * a4.x + c4.y * a4.y + c4.z * a4.z + c4.w * a4.w;
        }
        int gr = r0 + r;
        if (gr < NN) {
            if (isAd) ((float*)g_ad2)[2 * gr + enc] = acc;
            else      ((float*)g_as2)[2 * gr + enc] = acc;
        }
    }
}

// ---------------- single-pass dual-encoder GAT aggregation ------------------
// Split-lane: lanes 0-15 encoder 0 (4 cols each), lanes 16-31 encoder 1.
// writeF16: layers 1-2 emit fp16 x (identical precision to gemm-side quantize);
// last layer emits fp32 for final_kernel.
__global__ void __launch_bounds__(256) agg2_kernel(const float* __restrict__ bo,
                                                   const float* __restrict__ bt,
                                                   int writeF16) {
    int d = (blockIdx.x * blockDim.x + threadIdx.x) >> 5;
    int lane = threadIdx.x & 31;
    if (d >= NN) return;

    int encSel = lane >> 4;
    int li     = lane & 15;
    const uint2* hsel = encSel ? (const uint2*)g_h16[1] : (const uint2*)g_h16[0];

    int s0 = g_rowptr[d];
    int s1 = g_rowptr[d + 1];
    float2 adv = g_ad2[d];
    float2 asv = g_as2[d];
    float m0 = lrelu(asv.x + adv.x);
    float m1 = lrelu(asv.y + adv.y);

    uint2 hd = hsel[(size_t)d * 16 + li];
    float2 pa = __half22float2(*(__half2*)&hd.x);
    float2 pb = __half22float2(*(__half2*)&hd.y);
    float acc0 = pa.x, acc1 = pa.y, acc2 = pb.x, acc3 = pb.y;  // self message (w=1)
    float den0 = (lane == 0) ? 1.f : 0.f;
    float den1 = den0;

    for (int base = s0; base < s1; base += 32) {
        int k = base + lane;
        bool valid = k < s1;
        int s = valid ? __ldcs(&g_col[k]) : 0;
        float e0 = -1e30f, e1 = -1e30f;
        if (valid) {
            float2 a = g_as2[s];
            e0 = lrelu(a.x + adv.x);
            e1 = lrelu(a.y + adv.y);
        }
        float c0 = e0, c1 = e1;
#pragma unroll
        for (int o = 16; o; o >>= 1) {
            c0 = fmaxf(c0, __shfl_xor_sync(0xffffffffu, c0, o));
            c1 = fmaxf(c1, __shfl_xor_sync(0xffffffffu, c1, o));
        }
        if (c0 > m0) {
            float sc = __expf(m0 - c0);
            den0 *= sc;
            if (encSel == 0) { acc0 *= sc; acc1 *= sc; acc2 *= sc; acc3 *= sc; }
            m0 = c0;
        }
        if (c1 > m1) {
            float sc = __expf(m1 - c1);
            den1 *= sc;
            if (encSel == 1) { acc0 *= sc; acc1 *= sc; acc2 *= sc; acc3 *= sc; }
            m1 = c1;
        }

        float w0 = valid ? __expf(e0 - m0) : 0.f;
        float w1 = valid ? __expf(e1 - m1) : 0.f;
        den0 += w0;
        den1 += w1;

        int cnt = min(32, s1 - base);
        int padded = (cnt + 3) & ~3;
        for (int j = 0; j < padded; j += 4) {
            int sj0 = __shfl_sync(0xffffffffu, s, j + 0);
            int sj1 = __shfl_sync(0xffffffffu, s, j + 1);
            int sj2 = __shfl_sync(0xffffffffu, s, j + 2);
            int sj3 = __shfl_sync(0xffffffffu, s, j + 3);
            uint2 v0 = hsel[(size_t)sj0 * 16 + li];
            uint2 v1 = hsel[(size_t)sj1 * 16 + li];
            uint2 v2 = hsel[(size_t)sj2 * 16 + li];
            uint2 v3 = hsel[(size_t)sj3 * 16 + li];
            float w00 = __shfl_sync(0xffffffffu, w0, j + 0);
            float w10 = __shfl_sync(0xffffffffu, w1, j + 0);
            float w01 = __shfl_sync(0xffffffffu, w0, j + 1);
            float w11 = __shfl_sync(0xffffffffu, w1, j + 1);
            float w02 = __shfl_sync(0xffffffffu, w0, j + 2);
            float w12 = __shfl_sync(0xffffffffu, w1, j + 2);
            float w03 = __shfl_sync(0xffffffffu, w0, j + 3);
            float w13 = __shfl_sync(0xffffffffu, w1, j + 3);
            float ws0 = encSel ? w10 : w00;
            float ws1 = encSel ? w11 : w01;
            float ws2 = encSel ? w12 : w02;
            float ws3 = encSel ? w13 : w03;
            float2 p, q;
            p = __half22float2(*(__half2*)&v0.x); q = __half22float2(*(__half2*)&v0.y);
            acc0 = fmaf(ws0, p.x, acc0); acc1 = fmaf(ws0, p.y, acc1);
            acc2 = fmaf(ws0, q.x, acc2); acc3 = fmaf(ws0, q.y, acc3);
            p = __half22float2(*(__half2*)&v1.x); q = __half22float2(*(__half2*)&v1.y);
            acc0 = fmaf(ws1, p.x, acc0); acc1 = fmaf(ws1, p.y, acc1);
            acc2 = fmaf(ws1, q.x, acc2); acc3 = fmaf(ws1, q.y, acc3);
            p = __half22float2(*(__half2*)&v2.x); q = __half22float2(*(__half2*)&v2.y);
            acc0 = fmaf(ws2, p.x, acc0); acc1 = fmaf(ws2, p.y, acc1);
            acc2 = fmaf(ws2, q.x, acc2); acc3 = fmaf(ws2, q.y, acc3);
            p = __half22float2(*(__half2*)&v3.x); q = __half22float2(*(__half2*)&v3.y);
            acc0 = fmaf(ws3, p.x, acc0); acc1 = fmaf(ws3, p.y, acc1);
            acc2 = fmaf(ws3, q.x, acc2); acc3 = fmaf(ws3, q.y, acc3);
        }
    }
#pragma unroll
    for (int o = 16; o; o >>= 1) {
        den0 += __shfl_xor_sync(0xffffffffu, den0, o);
        den1 += __shfl_xor_sync(0xffffffffu, den1, o);
    }
    float inv = encSel ? (1.f / den1) : (1.f / den0);

    const float* bsel = encSel ? bt : bo;
    float4 b4 = ((const float4*)bsel)[li];
    float4 o;
    o.x = acc0 * inv + b4.x;
    o.y = acc1 * inv + b4.y;
    o.z = acc2 * inv + b4.z;
    o.w = acc3 * inv + b4.w;
    if (writeF16) {
        __half2 q0 = __floats2half2_rn(o.x, o.y);
        __half2 q1 = __floats2half2_rn(o.z, o.w);
        ((uint2*)g_x16[encSel])[(size_t)d * 16 + li] =
            make_uint2(*(unsigned*)&q0, *(unsigned*)&q1);
    } else {
        __stcs(&((float4*)g_x[encSel])[(size_t)d * 16 + li], o);
    }

    if (lane == 0) g_fill[d] = 0;   // reset counts for the next launch
}

// ---------------- predictor + output assembly ----------------
__global__ void __launch_bounds__(256) final_kernel(const float* __restrict__ pW,
                                                    const float* __restrict__ pb,
                                                    const int* __restrict__ user,
                                                    const int* __restrict__ item,
                                                    float* __restrict__ out) {
    __shared__ float Ws[64 * 65];
    __shared__ float rows[4 * 64];
    int tid = threadIdx.x;
    bool isU = blockIdx.x < (Q / 4);
    int qb = (isU ? blockIdx.x : blockIdx.x - (Q / 4)) * 4;

    for (int i = tid; i < 4096; i += 256) Ws[(i >> 6) * 65 + (i & 63)] = pW[i];

    int qr = tid >> 6, c = tid & 63;
    int q = qb + qr;
    int node = isU ? user[q] : (NUSER + item[q]);
    rows[qr * 64 + c] = g_x[0][(size_t)node * F + c];
    __syncthreads();

    float acc = pb[c];
#pragma unroll
    for (int k = 0; k < 64; k++) acc = fmaf(rows[qr * 64 + k], Ws[c * 65 + k], acc);

    size_t base = isU ? 0 : (size_t)2 * Q * F;
    out[base + (size_t)q * F + c] = acc;                                  // predicted
    out[base + (size_t)Q * F + (size_t)q * F + c] = g_x[1][(size_t)node * F + c];  // target
}

// ---------------- host ----------------
extern "C" void kernel_launch(void* const* d_in, const int* in_sizes, int n_in,
                              void* d_out, int out_size) {
    const float *uembo, *iembo, *Wo, *aso, *ado, *bo;
    const float *uembt, *iembt, *Wt, *ast, *adt, *bt;
    const float *pW, *pb;
    const int *user, *item, *ei;

    if (in_sizes[0] == Q) {  // setup_inputs dict order
        user  = (const int*)d_in[0];
        item  = (const int*)d_in[1];
        ei    = (const int*)d_in[2];
        uembo = (const float*)d_in[3];  iembo = (const float*)d_in[4];
        Wo    = (const float*)d_in[5];
        aso   = (const float*)d_in[6];  ado   = (const float*)d_in[7];  bo = (const float*)d_in[8];
        uembt = (const float*)d_in[9];  iembt = (const float*)d_in[10];
        Wt    = (const float*)d_in[11];
        ast   = (const float*)d_in[12]; adt   = (const float*)d_in[13]; bt = (const float*)d_in[14];
        pW    = (const float*)d_in[15]; pb    = (const float*)d_in[16];
    } else {                 // reference signature order
        uembo = (const float*)d_in[0];  iembo = (const float*)d_in[1];
        Wo    = (const float*)d_in[2];
        aso   = (const float*)d_in[3];  ado   = (const float*)d_in[4];  bo = (const float*)d_in[5];
        uembt = (const float*)d_in[6];  iembt = (const float*)d_in[7];
        Wt    = (const float*)d_in[8];
        ast   = (const float*)d_in[9];  adt   = (const float*)d_in[10]; bt = (const float*)d_in[11];
        pW    = (const float*)d_in[12]; pb    = (const float*)d_in[13];
        user  = (const int*)d_in[14];
        item  = (const int*)d_in[15];
        ei    = (const int*)d_in[16];
    }
    float* out = (float*)d_out;

    hist_kernel<<<EE / 256, 256>>>(ei);
    scan_kernel<<<1, 1024>>>();
    scatter_kernel<<<EE / 256, 256>>>(ei);

    const int GEMM_BLOCKS = (NN + GR - 1) / GR;  // 1172
    const int WARP_BLOCKS = NN / 8;              // 18750

    static __half* gx16_base = nullptr;
    if (!gx16_base) cudaGetSymbolAddress((void**)&gx16_base, g_x16);

    for (int l = 0; l < 3; l++) {
        dim3 gg(GEMM_BLOCKS, 2);
        const void *Xu0, *Xi0, *Xu1, *Xi1;
        int xf16 = (l != 0);
        if (l == 0) {
            Xu0 = uembo; Xi0 = iembo; Xu1 = uembt; Xi1 = iembt;
        } else {
            Xu0 = gx16_base;
            Xi0 = gx16_base + (size_t)NUSER * F;
            Xu1 = gx16_base + (size_t)NN * F;
            Xi1 = gx16_base + (size_t)NN * F + (size_t)NUSER * F;
        }
        gemm_dots_kernel<<<gg, 256>>>(Xu0, Xi0, Xu1, Xi1,
                                      Wo + (size_t)l * F * F, Wt + (size_t)l * F * F,
                                      aso + l * F, ado + l * F, ast + l * F, adt + l * F,
                                      xf16);
        agg2_kernel<<<WARP_BLOCKS, 256>>>(bo + l * F, bt + l * F, (l < 2) ? 1 : 0);
    }

    final_kernel<<<2 * (Q / 4), 256>>>(pW, pb, user, item, out);
}

// round 15
// speedup vs baseline: 1.3117x; 1.1980x over previous
#include <cuda_runtime.h>
#include <cuda_fp16.h>
#include <mma.h>
using namespace nvcuda;

#define NUSER 100000
#define NITEM 50000
#define NN    150000
#define EE    2400000
#define F     64
#define Q     4096
#define GR    128               // rows per gemm block
#define XSTR  72                // padded fp16 smem stride (halves): conflict-free LDSM
#define CSTR  68                // padded Cs row stride (floats)
#define NEG_SLOPE 0.2f

// ---------------- device scratch (no allocs allowed) ----------------
__device__ __align__(16) float  g_x[2][NN * F];     // fp32 x (final layer output)
__device__ __align__(16) __half g_x16[2][NN * F];   // fp16 x hand-off (layers 1-2)
__device__ __align__(16) __half g_h16[2][NN * F];   // dense fp16 h per encoder
__device__ __align__(8)  float2 g_as2[NN];          // (as_online, as_target) fp32
__device__ __align__(8)  float2 g_ad2[NN];          // (ad_online, ad_target) fp32
__device__ int g_rowptr[NN + 1];
__device__ int g_fill[NN];   // .bss zero at load; re-zeroed by agg2 each launch
__device__ int g_col[EE];

__device__ __forceinline__ float lrelu(float v) { return fmaxf(v, NEG_SLOPE * v); }

// ---------------- CSR build ----------------
__global__ void hist_kernel(const int* __restrict__ ei) {
    int i = blockIdx.x * blockDim.x + threadIdx.x;
    if (i < EE) atomicAdd(&g_fill[__ldcs(ei + EE + i)], 1);
}

__global__ void scan_kernel() {
    __shared__ int sb[1024];
    int t = threadIdx.x;
    const int CH = 147;
    int start = t * CH;
    int end = min(start + CH, NN);
    int s = 0;
    for (int i = start; i < end; i++) s += g_fill[i];
    sb[t] = s;
    __syncthreads();
    for (int o = 1; o < 1024; o <<= 1) {
        int v = 0;
        if (t >= o) v = sb[t - o];
        __syncthreads();
        if (t >= o) sb[t] += v;
        __syncthreads();
    }
    int run = (t == 0) ? 0 : sb[t - 1];
    for (int i = start; i < end; i++) {
        int cnt = g_fill[i];
        g_rowptr[i] = run;
        g_fill[i]   = run;
        run += cnt;
    }
    if (t == 1023) g_rowptr[NN] = sb[1023];
}

__global__ void scatter_kernel(const int* __restrict__ ei) {
    int i = blockIdx.x * blockDim.x + threadIdx.x;
    if (i < EE) {
        int d = __ldcs(ei + EE + i);
        int pos = atomicAdd(&g_fill[d], 1);
        g_col[pos] = __ldcs(ei + i);
    }
}

// ---------------- WMMA gemm (h = x @ W, fp16 in / fp32 acc) + fused dots ----
// smem: [0, 9216) W half stride 72 (reused as As/Ad floats after MMA);
//       [9216, 9216+18432) X half stride 72;  [9216, 44032) C float stride 68 (unions X).
__global__ void __launch_bounds__(256) gemm_dots_kernel(
    const void* __restrict__ Xu0, const void* __restrict__ Xi0,
    const void* __restrict__ Xu1, const void* __restrict__ Xi1,
    const float* __restrict__ Wo, const float* __restrict__ Wt,
    const float* __restrict__ aso, const float* __restrict__ ado,
    const float* __restrict__ ast, const float* __restrict__ adt,
    int xIsF16) {
    int enc = blockIdx.y;
    const float* W   = enc ? Wt  : Wo;
    const float* avs = enc ? ast : aso;
    const float* avd = enc ? adt : ado;
    const void* Xu   = enc ? Xu1 : Xu0;
    const void* Xi   = enc ? Xi1 : Xi0;

    __shared__ __align__(16) char smem[44032];
    half*  Wh   = (half*)smem;                 // 64 x stride 72
    float* Avec = (float*)smem;                // 128 floats, written AFTER mma reads Wh
    half*  Xh   = (half*)(smem + 9216);        // 128 x stride 72
    float* Cs   = (float*)(smem + 9216);       // 128 x stride 68 (unions Xh)

    int tid = threadIdx.x;
    int r0  = blockIdx.x * GR;

    // load W (64x64 fp32 -> fp16), stride-72 smem
    {
        const float4* W4 = (const float4*)W;
#pragma unroll
        for (int i = 0; i < 4; i++) {
            int idx = tid + i * 256;             // float4 index, 1024 total
            int row = idx >> 4, q = idx & 15;
            float4 v = W4[idx];
            __half2 a = __floats2half2_rn(v.x, v.y);
            __half2 b = __floats2half2_rn(v.z, v.w);
            *(uint2*)(Wh + row * XSTR + q * 4) = make_uint2(*(unsigned*)&a, *(unsigned*)&b);
        }
    }
    // load X tile (GR x 64) -> fp16 smem stride 72; src fp32 (layer 0) or fp16 (layers 1+)
    if (xIsF16) {
        const uint4* XuH = (const uint4*)Xu;     // 8 halves per uint4
        const uint4* XiH = (const uint4*)Xi;
#pragma unroll
        for (int i = 0; i < 4; i++) {
            int idx = tid + i * 256;             // uint4 index, 1024 total
            int row = idx >> 3, q = idx & 7;
            int gr  = r0 + row;
            uint4 v = make_uint4(0u, 0u, 0u, 0u);
            if (gr < NUSER)   v = __ldcs(XuH + (size_t)gr * 8 + q);
            else if (gr < NN) v = __ldcs(XiH + (size_t)(gr - NUSER) * 8 + q);
            *(uint4*)(Xh + row * XSTR + q * 8) = v;
        }
    } else {
        const float4* XuF = (const float4*)Xu;
        const float4* XiF = (const float4*)Xi;
#pragma unroll
        for (int i = 0; i < 8; i++) {
            int idx = tid + i * 256;             // float4 index, 2048 total
            int row = idx >> 4, q = idx & 15;
            int gr  = r0 + row;
            float4 v = make_float4(0.f, 0.f, 0.f, 0.f);
            if (gr < NUSER)   v = __ldcs(XuF + (size_t)gr * 16 + q);
            else if (gr < NN) v = __ldcs(XiF + (size_t)(gr - NUSER) * 16 + q);
            __half2 a = __floats2half2_rn(v.x, v.y);
            __half2 b = __floats2half2_rn(v.z, v.w);
            *(uint2*)(Xh + row * XSTR + q * 4) = make_uint2(*(unsigned*)&a, *(unsigned*)&b);
        }
    }
    __syncthreads();

    int wid = tid >> 5;

    wmma::fragment<wmma::accumulator, 16, 16, 16, float> cfrag[4];
#pragma unroll
    for (int n = 0; n < 4; n++) wmma::fill_fragment(cfrag[n], 0.0f);
#pragma unroll
    for (int k = 0; k < 4; k++) {
        wmma::fragment<wmma::matrix_a, 16, 16, 16, half, wmma::row_major> afrag;
        wmma::load_matrix_sync(afrag, Xh + (wid * 16) * XSTR + k * 16, XSTR);
#pragma unroll
        for (int n = 0; n < 4; n++) {
            wmma::fragment<wmma::matrix_b, 16, 16, 16, half, wmma::row_major> bfrag;
            wmma::load_matrix_sync(bfrag, Wh + (k * 16) * XSTR + n * 16, XSTR);
            wmma::mma_sync(cfrag[n], afrag, bfrag, cfrag[n]);
        }
    }
    __syncthreads();   // all reads of Wh/Xh done

    // stage attention vectors into (now dead) W region; store C tiles
    if (tid < 64)       Avec[tid] = avs[tid];
    else if (tid < 128) Avec[tid] = avd[tid - 64];
#pragma unroll
    for (int n = 0; n < 4; n++)
        wmma::store_matrix_sync(Cs + (wid * 16) * CSTR + n * 16, cfrag[n], CSTR, wmma::mem_row_major);
    __syncthreads();

    // dense fp16 h store: thread handles 4 (row, 8-col-group) items.
    __half* Hd = g_h16[enc];
#pragma unroll
    for (int i = 0; i < 4; i++) {
        int idx = tid + i * 256;                 // 0..1023 items
        int r   = idx >> 3;
        int g   = ((idx & 7) + r) & 7;           // swizzled column group
        int gr  = r0 + r;
        if (gr < NN) {
            const float4* src = (const float4*)(Cs + r * CSTR + g * 8);
            float4 f0 = src[0], f1 = src[1];
            __half2 a  = __floats2half2_rn(f0.x, f0.y);
            __half2 b  = __floats2half2_rn(f0.z, f0.w);
            __half2 c2 = __floats2half2_rn(f1.x, f1.y);
            __half2 d2 = __floats2half2_rn(f1.z, f1.w);
            *(uint4*)(Hd + (size_t)gr * F + g * 8) =
                make_uint4(*(unsigned*)&a, *(unsigned*)&b, *(unsigned*)&c2, *(unsigned*)&d2);
        }
    }

    // shuffle-free dots: threads 0-127 -> as[row], threads 128-255 -> ad[row].
    {
        int r = tid & 127;
        bool isAd = tid >= 128;
        const float4* row4 = (const float4*)(Cs + r * CSTR);
        const float4* av4  = (const float4*)(Avec + (isAd ? 64 : 0));
        float acc = 0.f;
#pragma unroll
        for (int i = 0; i < 16; i++) {
            float4 c4 = row4[i];
            float4 a4 = av4[i];
            acc += c4.x * a4.x + c4.y * a4.y + c4.z * a4.z + c4.w * a4.w;
        }
        int gr = r0 + r;
        if (gr < NN) {
            if (isAd) ((float*)g_ad2)[2 * gr + enc] = acc;
            else      ((float*)g_as2)[2 * gr + enc] = acc;
        }
    }
}

// ---------------- single-pass dual-encoder GAT aggregation ------------------
// No max subtraction: logits are xavier-scale (|e| << ln(FLT_MAX)), exp is
// overflow-safe and the result is mathematically identical to the stabilized
// softmax. Split-lane: lanes 0-15 encoder 0 (4 cols each), lanes 16-31 enc 1.
__global__ void __launch_bounds__(256) agg2_kernel(const float* __restrict__ bo,
                                                   const float* __restrict__ bt,
                                                   int writeF16) {
    int d = (blockIdx.x * blockDim.x + threadIdx.x) >> 5;
    int lane = threadIdx.x & 31;
    if (d >= NN) return;

    int encSel = lane >> 4;
    int li     = lane & 15;
    const uint2* hsel = encSel ? (const uint2*)g_h16[1] : (const uint2*)g_h16[0];

    int s0 = g_rowptr[d];
    int s1 = g_rowptr[d + 1];
    float2 adv = g_ad2[d];
    float2 asv = g_as2[d];
    float w0s = __expf(lrelu(asv.x + adv.x));
    float w1s = __expf(lrelu(asv.y + adv.y));
    float wself = encSel ? w1s : w0s;

    uint2 hd = hsel[(size_t)d * 16 + li];
    float2 pa = __half22float2(*(__half2*)&hd.x);
    float2 pb = __half22float2(*(__half2*)&hd.y);
    float acc0 = wself * pa.x, acc1 = wself * pa.y;
    float acc2 = wself * pb.x, acc3 = wself * pb.y;
    float den0 = (lane == 0) ? w0s : 0.f;
    float den1 = (lane == 0) ? w1s : 0.f;

    for (int base = s0; base < s1; base += 32) {
        int k = base + lane;
        bool valid = k < s1;
        int s = valid ? g_col[k] : 0;
        float w0 = 0.f, w1 = 0.f;
        if (valid) {
            float2 a = g_as2[s];
            w0 = __expf(lrelu(a.x + adv.x));
            w1 = __expf(lrelu(a.y + adv.y));
        }
        den0 += w0;
        den1 += w1;

        int cnt = min(32, s1 - base);
        int padded = (cnt + 3) & ~3;     // padded lanes carry w=0, s=0 -> no-ops
        for (int j = 0; j < padded; j += 4) {
            int sj0 = __shfl_sync(0xffffffffu, s, j + 0);
            int sj1 = __shfl_sync(0xffffffffu, s, j + 1);
            int sj2 = __shfl_sync(0xffffffffu, s, j + 2);
            int sj3 = __shfl_sync(0xffffffffu, s, j + 3);
            uint2 v0 = hsel[(size_t)sj0 * 16 + li];
            uint2 v1 = hsel[(size_t)sj1 * 16 + li];
            uint2 v2 = hsel[(size_t)sj2 * 16 + li];
            uint2 v3 = hsel[(size_t)sj3 * 16 + li];
            float w00 = __shfl_sync(0xffffffffu, w0, j + 0);
            float w10 = __shfl_sync(0xffffffffu, w1, j + 0);
            float w01 = __shfl_sync(0xffffffffu, w0, j + 1);
            float w11 = __shfl_sync(0xffffffffu, w1, j + 1);
            float w02 = __shfl_sync(0xffffffffu, w0, j + 2);
            float w12 = __shfl_sync(0xffffffffu, w1, j + 2);
            float w03 = __shfl_sync(0xffffffffu, w0, j + 3);
            float w13 = __shfl_sync(0xffffffffu, w1, j + 3);
            float ws0 = encSel ? w10 : w00;
            float ws1 = encSel ? w11 : w01;
            float ws2 = encSel ? w12 : w02;
            float ws3 = encSel ? w13 : w03;
            float2 p, q;
            p = __half22float2(*(__half2*)&v0.x); q = __half22float2(*(__half2*)&v0.y);
            acc0 = fmaf(ws0, p.x, acc0); acc1 = fmaf(ws0, p.y, acc1);
            acc2 = fmaf(ws0, q.x, acc2); acc3 = fmaf(ws0, q.y, acc3);
            p = __half22float2(*(__half2*)&v1.x); q = __half22float2(*(__half2*)&v1.y);
            acc0 = fmaf(ws1, p.x, acc0); acc1 = fmaf(ws1, p.y, acc1);
            acc2 = fmaf(ws1, q.x, acc2); acc3 = fmaf(ws1, q.y, acc3);
            p = __half22float2(*(__half2*)&v2.x); q = __half22float2(*(__half2*)&v2.y);
            acc0 = fmaf(ws2, p.x, acc0); acc1 = fmaf(ws2, p.y, acc1);
            acc2 = fmaf(ws2, q.x, acc2); acc3 = fmaf(ws2, q.y, acc3);
            p = __half22float2(*(__half2*)&v3.x); q = __half22float2(*(__half2*)&v3.y);
            acc0 = fmaf(ws3, p.x, acc0); acc1 = fmaf(ws3, p.y, acc1);
            acc2 = fmaf(ws3, q.x, acc2); acc3 = fmaf(ws3, q.y, acc3);
        }
    }
#pragma unroll
    for (int o = 16; o; o >>= 1) {
        den0 += __shfl_xor_sync(0xffffffffu, den0, o);
        den1 += __shfl_xor_sync(0xffffffffu, den1, o);
    }
    float inv = encSel ? (1.f / den1) : (1.f / den0);

    const float* bsel = encSel ? bt : bo;
    float4 b4 = ((const float4*)bsel)[li];
    float4 o;
    o.x = acc0 * inv + b4.x;
    o.y = acc1 * inv + b4.y;
    o.z = acc2 * inv + b4.z;
    o.w = acc3 * inv + b4.w;
    if (writeF16) {
        __half2 q0 = __floats2half2_rn(o.x, o.y);
        __half2 q1 = __floats2half2_rn(o.z, o.w);
        ((uint2*)g_x16[encSel])[(size_t)d * 16 + li] =
            make_uint2(*(unsigned*)&q0, *(unsigned*)&q1);
    } else {
        __stcs(&((float4*)g_x[encSel])[(size_t)d * 16 + li], o);
    }

    if (lane == 0) g_fill[d] = 0;   // reset counts for the next launch
}

// ---------------- predictor + output assembly ----------------
__global__ void __launch_bounds__(256) final_kernel(const float* __restrict__ pW,
                                                    const float* __restrict__ pb,
                                                    const int* __restrict__ user,
                                                    const int* __restrict__ item,
                                                    float* __restrict__ out) {
    __shared__ float Ws[64 * 65];
    __shared__ float rows[4 * 64];
    int tid = threadIdx.x;
    bool isU = blockIdx.x < (Q / 4);
    int qb = (isU ? blockIdx.x : blockIdx.x - (Q / 4)) * 4;

    for (int i = tid; i < 4096; i += 256) Ws[(i >> 6) * 65 + (i & 63)] = pW[i];

    int qr = tid >> 6, c = tid & 63;
    int q = qb + qr;
    int node = isU ? user[q] : (NUSER + item[q]);
    rows[qr * 64 + c] = g_x[0][(size_t)node * F + c];
    __syncthreads();

    float acc = pb[c];
#pragma unroll
    for (int k = 0; k < 64; k++) acc = fmaf(rows[qr * 64 + k], Ws[c * 65 + k], acc);

    size_t base = isU ? 0 : (size_t)2 * Q * F;
    out[base + (size_t)q * F + c] = acc;                                  // predicted
    out[base + (size_t)Q * F + (size_t)q * F + c] = g_x[1][(size_t)node * F + c];  // target
}

// ---------------- host ----------------
extern "C" void kernel_launch(void* const* d_in, const int* in_sizes, int n_in,
                              void* d_out, int out_size) {
    const float *uembo, *iembo, *Wo, *aso, *ado, *bo;
    const float *uembt, *iembt, *Wt, *ast, *adt, *bt;
    const float *pW, *pb;
    const int *user, *item, *ei;

    if (in_sizes[0] == Q) {  // setup_inputs dict order
        user  = (const int*)d_in[0];
        item  = (const int*)d_in[1];
        ei    = (const int*)d_in[2];
        uembo = (const float*)d_in[3];  iembo = (const float*)d_in[4];
        Wo    = (const float*)d_in[5];
        aso   = (const float*)d_in[6];  ado   = (const float*)d_in[7];  bo = (const float*)d_in[8];
        uembt = (const float*)d_in[9];  iembt = (const float*)d_in[10];
        Wt    = (const float*)d_in[11];
        ast   = (const float*)d_in[12]; adt   = (const float*)d_in[13]; bt = (const float*)d_in[14];
        pW    = (const float*)d_in[15]; pb    = (const float*)d_in[16];
    } else {                 // reference signature order
        uembo = (const float*)d_in[0];  iembo = (const float*)d_in[1];
        Wo    = (const float*)d_in[2];
        aso   = (const float*)d_in[3];  ado   = (const float*)d_in[4];  bo = (const float*)d_in[5];
        uembt = (const float*)d_in[6];  iembt = (const float*)d_in[7];
        Wt    = (const float*)d_in[8];
        ast   = (const float*)d_in[9];  adt   = (const float*)d_in[10]; bt = (const float*)d_in[11];
        pW    = (const float*)d_in[12]; pb    = (const float*)d_in[13];
        user  = (const int*)d_in[14];
        item  = (const int*)d_in[15];
        ei    = (const int*)d_in[16];
    }
    float* out = (float*)d_out;

    hist_kernel<<<EE / 256, 256>>>(ei);
    scan_kernel<<<1, 1024>>>();
    scatter_kernel<<<EE / 256, 256>>>(ei);

    const int GEMM_BLOCKS = (NN + GR - 1) / GR;  // 1172
    const int WARP_BLOCKS = NN / 8;              // 18750

    static __half* gx16_base = nullptr;
    if (!gx16_base) cudaGetSymbolAddress((void**)&gx16_base, g_x16);

    for (int l = 0; l < 3; l++) {
        dim3 gg(GEMM_BLOCKS, 2);
        const void *Xu0, *Xi0, *Xu1, *Xi1;
        int xf16 = (l != 0);
        if (l == 0) {
            Xu0 = uembo; Xi0 = iembo; Xu1 = uembt; Xi1 = iembt;
        } else {
            Xu0 = gx16_base;
            Xi0 = gx16_base + (size_t)NUSER * F;
            Xu1 = gx16_base + (size_t)NN * F;
            Xi1 = gx16_base + (size_t)NN * F + (size_t)NUSER * F;
        }
        gemm_dots_kernel<<<gg, 256>>>(Xu0, Xi0, Xu1, Xi1,
                                      Wo + (size_t)l * F * F, Wt + (size_t)l * F * F,
                                      aso + l * F, ado + l * F, ast + l * F, adt + l * F,
                                      xf16);
        agg2_kernel<<<WARP_BLOCKS, 256>>>(bo + l * F, bt + l * F, (l < 2) ? 1 : 0);
    }

    final_kernel<<<2 * (Q / 4), 256>>>(pW, pb, user, item, out);
}